// round 16
// baseline (speedup 1.0000x reference)
#include <cuda_runtime.h>
#include <cuda_fp16.h>
#include <math.h>
#include <stdint.h>

#define Bn 32
#define Tn 1024
#define Dn 512
#define Gn 256
#define En 8
#define Vn 8192

#define BM 128
#define BN 128
#define BK 32
#define FTHREADS 128
#define NTHREADS 256

#define L2E 1.4426950408889634f
#define LN2 0.6931471805599453f

// smem strides (bytes), padded for conflict-free ldmatrix
#define A_STRIDE 80
#define B_STRIDE 272
#define A_BYTES (BM * A_STRIDE)          // 10240
#define B_BYTES (BK * B_STRIDE)          // 8704
#define STAGE_BYTES (A_BYTES + B_BYTES)  // 18944
#define NSTAGES 3
#define SM_MBAR (NSTAGES * STAGE_BYTES)  // 56832
#define SMEM_BYTES (SM_MBAR + 64)        // 56896 per CTA, 4 CTAs/SM

// fused grid layout (bid ranges), 128 threads per block
#define NB_ROUTER 1
#define NB_Z 16                 // zero g_sumexp: 8192 f4 / (128*4)
#define NB_X 4096               // X out: 2,097,152 uint4 / (128*4); 128 blocks/sample
#define NB_W 8192               // W out: 4,194,304 uint4 / (128*4); 1024 blocks/expert
#define ZBASE  NB_ROUTER
#define XBASE  (ZBASE + NB_Z)            // 17
#define WBASE  (XBASE + NB_X)            // 4113
#define GBASE  (WBASE + NB_W)            // 12305
#define NB_GEMM 16384                    // 64 vt * 8 tt * 32 b
#define NB_TOTAL (GBASE + NB_GEMM)       // 28689

// ---------------- scratch (no cudaMalloc allowed) ----------------
__device__ __half g_Xh[(size_t)Bn * Tn * Dn];
__device__ __half g_Wh[(size_t)En * Dn * Vn];
__device__ float g_sumexp[Bn * Tn];
__device__ float g_tgt[Bn * Tn];                // stores logit * log2(e)
__device__ int   g_assign[Bn];
__device__ float g_ce[Bn];
__device__ int   g_cnt;
__device__ int   g_rdone;
__device__ int   g_zcnt;
__device__ int   g_xcnt[Bn];
__device__ int   g_wcnt[En];

// ---------------- helpers ----------------
__device__ __forceinline__ uint32_t s2u(const void* p) {
    uint32_t a;
    asm("{ .reg .u64 t; cvta.to.shared.u64 t, %1; cvt.u32.u64 %0, t; }" : "=r"(a) : "l"(p));
    return a;
}
__device__ __forceinline__ void cp16(uint32_t dst, const void* src) {
    asm volatile("cp.async.cg.shared.global [%0], [%1], 16;" :: "r"(dst), "l"(src) : "memory");
}
__device__ __forceinline__ void mwait(uint32_t addr, uint32_t phase) {
    asm volatile(
        "{\n\t.reg .pred P;\n\t"
        "WL_%=:\n\t"
        "mbarrier.try_wait.parity.acquire.cta.shared::cta.b64 P, [%0], %1, 0x989680;\n\t"
        "@P bra WD_%=;\n\t"
        "bra WL_%=;\n\t"
        "WD_%=:\n\t}"
        :: "r"(addr), "r"(phase) : "memory");
}
__device__ __forceinline__ void mbar_init(uint32_t a, uint32_t cnt) {
    asm volatile("mbarrier.init.shared::cta.b64 [%0], %1;" :: "r"(a), "r"(cnt) : "memory");
}
__device__ __forceinline__ void mbar_arrive(uint32_t a) {
    asm volatile("mbarrier.arrive.shared::cta.b64 _, [%0];" :: "r"(a) : "memory");
}
__device__ __forceinline__ void cpasync_arrive(uint32_t a) {
    asm volatile("cp.async.mbarrier.arrive.noinc.shared::cta.b64 [%0];" :: "r"(a) : "memory");
}
__device__ __forceinline__ void ldsm_x4(uint32_t& r0, uint32_t& r1, uint32_t& r2, uint32_t& r3, uint32_t a) {
    asm volatile("ldmatrix.sync.aligned.m8n8.x4.shared.b16 {%0,%1,%2,%3}, [%4];"
                 : "=r"(r0), "=r"(r1), "=r"(r2), "=r"(r3) : "r"(a));
}
__device__ __forceinline__ void ldsm_x4t(uint32_t& r0, uint32_t& r1, uint32_t& r2, uint32_t& r3, uint32_t a) {
    asm volatile("ldmatrix.sync.aligned.m8n8.x4.trans.shared.b16 {%0,%1,%2,%3}, [%4];"
                 : "=r"(r0), "=r"(r1), "=r"(r2), "=r"(r3) : "r"(a));
}
__device__ __forceinline__ void mma_f16(uint32_t* d, const uint32_t* a, const uint32_t* b) {
    asm volatile("mma.sync.aligned.m16n8k16.row.col.f16.f16.f16.f16 "
                 "{%0,%1}, {%2,%3,%4,%5}, {%6,%7}, {%0,%1};"
                 : "+r"(d[0]), "+r"(d[1])
                 : "r"(a[0]), "r"(a[1]), "r"(a[2]), "r"(a[3]), "r"(b[0]), "r"(b[1]));
}
__device__ __forceinline__ __half2 h2ex2(__half2 x) {
    __half2 r;
    asm("ex2.approx.f16x2 %0, %1;" : "=r"(*(uint32_t*)&r) : "r"(*(uint32_t*)&x));
    return r;
}
__device__ __forceinline__ uint32_t h2u(__half2 h) { return *(uint32_t*)&h; }
__device__ __forceinline__ int ldacq(const int* p) {
    int v;
    asm volatile("ld.acquire.gpu.global.b32 %0, [%1];" : "=r"(v) : "l"(p) : "memory");
    return v;
}
__device__ __forceinline__ void red_rel(int* p) {
    asm volatile("red.release.gpu.global.add.s32 [%0], 1;" :: "l"(p) : "memory");
}

// ---------------- fused kernel: prep blocks + gemm blocks ----------------
__global__ void __launch_bounds__(FTHREADS, 4)
fused_kernel(const float4* __restrict__ X4,
             const float4* __restrict__ W4,
             const float* __restrict__ gate,
             const float* __restrict__ Wg,
             const float* __restrict__ bg,
             const float* __restrict__ be,
             const int* __restrict__ tgt32,
             float* __restrict__ out, int out_size)
{
    const int bid = blockIdx.x;
    const int tid = threadIdx.x;

    if (bid < NB_ROUTER) {
        // ---- router: logits, softmax, argmax; zero out buffer ----
        for (int i = tid; i < out_size; i += FTHREADS) out[i] = 0.0f;

        __shared__ float logits[Bn][En];
        #pragma unroll
        for (int s = 0; s < 2; s++) {
            int idx = s * FTHREADS + tid;
            int i = idx >> 3, j = idx & 7;
            float acc = bg[j];
            const float* grow = gate + i * Gn;
            #pragma unroll 4
            for (int g = 0; g < Gn; g++) acc += grow[g] * Wg[g * En + j];
            logits[i][j] = acc;
        }
        __syncthreads();
        if (tid < Bn) {
            float mx = logits[tid][0];
            int am = 0;
            #pragma unroll
            for (int e = 1; e < En; e++) {
                float v = logits[tid][e];
                if (v > mx) { mx = v; am = e; }
            }
            float ex[En], s = 0.0f;
            #pragma unroll
            for (int e = 0; e < En; e++) { ex[e] = expf(logits[tid][e] - mx); s += ex[e]; }
            float inv = 1.0f / s;
            #pragma unroll
            for (int e = 0; e < En; e++) out[1 + Bn + tid * En + e] = ex[e] * inv;
            out[1 + tid] = (float)am;
            g_assign[tid] = am;
        }
        __threadfence();
        __syncthreads();
        if (tid == 0) red_rel(&g_rdone);
        return;
    }
    if (bid < XBASE) {
        // ---- zero g_sumexp ----
        int zbid = bid - ZBASE;
        float4 z = make_float4(0.f, 0.f, 0.f, 0.f);
        #pragma unroll
        for (int k = 0; k < 4; k++)
            ((float4*)g_sumexp)[zbid * 512 + k * 128 + tid] = z;
        __threadfence();
        __syncthreads();
        if (tid == 0) red_rel(&g_zcnt);
        return;
    }
    if (bid < WBASE) {
        // ---- convert X: 512 out-uint4 per block ----
        int xbid = bid - XBASE;
        size_t o0 = (size_t)xbid * 512 + tid;
        float4 a[4], bb[4];
        #pragma unroll
        for (int k = 0; k < 4; k++) {
            size_t o = o0 + k * 128;
            a[k]  = X4[2 * o];
            bb[k] = X4[2 * o + 1];
        }
        uint4* ov = (uint4*)g_Xh;
        #pragma unroll
        for (int k = 0; k < 4; k++) {
            uint4 u;
            u.x = h2u(__floats2half2_rn(a[k].x, a[k].y));
            u.y = h2u(__floats2half2_rn(a[k].z, a[k].w));
            u.z = h2u(__floats2half2_rn(bb[k].x, bb[k].y));
            u.w = h2u(__floats2half2_rn(bb[k].z, bb[k].w));
            ov[o0 + k * 128] = u;
        }
        __threadfence();
        __syncthreads();
        if (tid == 0) red_rel(&g_xcnt[xbid >> 7]);   // 128 blocks per sample
        return;
    }
    if (bid < GBASE) {
        // ---- convert W: 512 out-uint4 per block; expert-major ----
        int wbid = bid - WBASE;
        size_t o0 = (size_t)wbid * 512 + tid;
        float4 a[4], bb[4];
        #pragma unroll
        for (int k = 0; k < 4; k++) {
            size_t o = o0 + k * 128;
            a[k]  = W4[2 * o];
            bb[k] = W4[2 * o + 1];
        }
        uint4* ov = (uint4*)g_Wh;
        #pragma unroll
        for (int k = 0; k < 4; k++) {
            uint4 u;
            u.x = h2u(__floats2half2_rn(a[k].x, a[k].y));
            u.y = h2u(__floats2half2_rn(a[k].z, a[k].w));
            u.z = h2u(__floats2half2_rn(bb[k].x, bb[k].y));
            u.w = h2u(__floats2half2_rn(bb[k].z, bb[k].w));
            ov[o0 + k * 128] = u;
        }
        __threadfence();
        __syncthreads();
        if (tid == 0) red_rel(&g_wcnt[wbid >> 10]);  // 1024 blocks per expert
        return;
    }

    // ================= GEMM + CE epilogue (R10 shape) =================
    extern __shared__ char smem[];
    const uint32_t sbase = s2u(smem);
    const uint32_t mbase = sbase + SM_MBAR;
    const int wid  = tid >> 5;
    const int lane = tid & 31;
    const int wm   = wid >> 1;
    const int wn   = wid & 1;

    const int g  = bid - GBASE;
    const int vt = g & 63;
    const int tt = (g >> 6) & 7;
    const int b  = g >> 9;
    const int v0 = vt * BN;
    const int t0 = tt * BM;

    // wait: router done
    if (tid == 0) {
        while (!ldacq(&g_rdone)) __nanosleep(128);
    }
    __syncthreads();
    const int e = g_assign[b];

    // wait: zeroing + this sample's X + this expert's W
    if (tid == 0) {
        while (ldacq(&g_zcnt)    < NB_Z) __nanosleep(128);
        while (ldacq(&g_xcnt[b]) < 128)  __nanosleep(128);
        while (ldacq(&g_wcnt[e]) < 1024) __nanosleep(256);
        #pragma unroll
        for (int s = 0; s < NSTAGES; s++) {
            mbar_init(mbase + s * 16,     128);
            mbar_init(mbase + s * 16 + 8, 4);
        }
    }
    __syncthreads();

    const __half* Ag = g_Xh + ((size_t)b * Tn + t0) * Dn;
    const __half* Bg = g_Wh + (size_t)e * Dn * Vn + v0;

    uint32_t acc[4][8][2];
    #pragma unroll
    for (int mt = 0; mt < 4; mt++)
        #pragma unroll
        for (int nt = 0; nt < 8; nt++) { acc[mt][nt][0] = 0u; acc[mt][nt][1] = 0u; }

    const uint32_t a_lane_off = (uint32_t)((lane & 15) * A_STRIDE + (lane >> 4) * 16)
                              + (uint32_t)(wm * 64 * A_STRIDE);
    const uint32_t b_lane_off = (uint32_t)((lane & 15) * B_STRIDE
                              + (wn * 64 + (lane >> 4) * 8) * 2);

    uint32_t prod_ph = 7u;
    uint32_t cons_ph = 0u;

    // producer prologue (all 128 threads act as producers)
    #pragma unroll
    for (int k = 0; k < 2; k++) {
        mwait(mbase + k * 16 + 8, (prod_ph >> k) & 1u);
        prod_ph ^= (1u << k);
        {
            uint32_t sA = sbase + k * STAGE_BYTES;
            uint32_t sB = sA + A_BYTES;
            #pragma unroll
            for (int i = 0; i < 4; i++) {
                int s = tid + i * FTHREADS;
                int row = s >> 2, j = s & 3;
                cp16(sA + (uint32_t)(row * A_STRIDE + j * 16),
                     Ag + (size_t)row * Dn + k * BK + j * 8);
            }
            #pragma unroll
            for (int i = 0; i < 4; i++) {
                int s = tid + i * FTHREADS;
                int kr = s >> 4, j = s & 15;
                cp16(sB + (uint32_t)(kr * B_STRIDE + j * 16),
                     Bg + (size_t)(k * BK + kr) * Vn + j * 8);
            }
        }
        cpasync_arrive(mbase + k * 16);
    }

    const int NCHUNK = Dn / BK;   // 16
    int ps = 2, cs = 0;
    #pragma unroll 1
    for (int c = 0; c < NCHUNK; c++) {
        if (c + 2 < NCHUNK) {
            mwait(mbase + ps * 16 + 8, (prod_ph >> ps) & 1u);
            prod_ph ^= (1u << ps);
            {
                uint32_t sA = sbase + ps * STAGE_BYTES;
                uint32_t sB = sA + A_BYTES;
                int k0 = (c + 2) * BK;
                #pragma unroll
                for (int i = 0; i < 4; i++) {
                    int s = tid + i * FTHREADS;
                    int row = s >> 2, j = s & 3;
                    cp16(sA + (uint32_t)(row * A_STRIDE + j * 16),
                         Ag + (size_t)row * Dn + k0 + j * 8);
                }
                #pragma unroll
                for (int i = 0; i < 4; i++) {
                    int s = tid + i * FTHREADS;
                    int kr = s >> 4, j = s & 15;
                    cp16(sB + (uint32_t)(kr * B_STRIDE + j * 16),
                         Bg + (size_t)(k0 + kr) * Vn + j * 8);
                }
            }
            cpasync_arrive(mbase + ps * 16);
            if (++ps == NSTAGES) ps = 0;
        }

        mwait(mbase + cs * 16, (cons_ph >> cs) & 1u);
        cons_ph ^= (1u << cs);

        const uint32_t aBase = sbase + cs * STAGE_BYTES + a_lane_off;
        const uint32_t bBase = sbase + cs * STAGE_BYTES + A_BYTES + b_lane_off;

        #pragma unroll
        for (int kt = 0; kt < 2; kt++) {
            uint32_t af[4][4], bf[16];
            #pragma unroll
            for (int mt = 0; mt < 4; mt++)
                ldsm_x4(af[mt][0], af[mt][1], af[mt][2], af[mt][3],
                        aBase + (uint32_t)(mt * 16 * A_STRIDE + kt * 32));
            #pragma unroll
            for (int gg = 0; gg < 4; gg++)
                ldsm_x4t(bf[gg * 4 + 0], bf[gg * 4 + 1], bf[gg * 4 + 2], bf[gg * 4 + 3],
                         bBase + (uint32_t)(kt * 16 * B_STRIDE + gg * 32));
            #pragma unroll
            for (int mt = 0; mt < 4; mt++)
                #pragma unroll
                for (int nt = 0; nt < 8; nt++)
                    mma_f16(acc[mt][nt], af[mt], &bf[nt * 2]);
        }

        __syncwarp();
        if (lane == 0) mbar_arrive(mbase + cs * 16 + 8);
        if (++cs == NSTAGES) cs = 0;
    }

    // ---- epilogue ----
    const int c0 = (lane & 3) * 2;
    const int r0 = lane >> 2;
    const int vbase = v0 + wn * 64 + c0;
    const float* bias_base = be + (size_t)e * Vn + vbase;

    const __half2 l2e = __float2half2_rn(L2E);
    __half2 bsc[8];
    #pragma unroll
    for (int nt = 0; nt < 8; nt++)
        bsc[nt] = __floats2half2_rn(bias_base[nt * 8] * L2E, bias_base[nt * 8 + 1] * L2E);

    #pragma unroll
    for (int mt = 0; mt < 4; mt++) {
        const int row0 = t0 + wm * 64 + mt * 16 + r0;
        const int row1 = row0 + 8;
        const int d0 = tgt32[2 * (b * Tn + row0)] - vbase;
        const int d1 = tgt32[2 * (b * Tn + row1)] - vbase;
        float s0 = 0.0f, s1 = 0.0f;
        #pragma unroll
        for (int nt = 0; nt < 8; nt++) {
            __half2 a0 = *(__half2*)&acc[mt][nt][0];
            __half2 a1 = *(__half2*)&acc[mt][nt][1];
            __half2 t0h = __hfma2(a0, l2e, bsc[nt]);
            __half2 t1h = __hfma2(a1, l2e, bsc[nt]);
            float2 e0 = __half22float2(h2ex2(t0h));
            float2 e1 = __half22float2(h2ex2(t1h));
            s0 += e0.x + e0.y;
            s1 += e1.x + e1.y;
            if (d0 == nt * 8)     g_tgt[(size_t)b * Tn + row0] = __low2float(t0h);
            if (d0 == nt * 8 + 1) g_tgt[(size_t)b * Tn + row0] = __high2float(t0h);
            if (d1 == nt * 8)     g_tgt[(size_t)b * Tn + row1] = __low2float(t1h);
            if (d1 == nt * 8 + 1) g_tgt[(size_t)b * Tn + row1] = __high2float(t1h);
        }
        s0 += __shfl_xor_sync(0xffffffffu, s0, 1);
        s0 += __shfl_xor_sync(0xffffffffu, s0, 2);
        s1 += __shfl_xor_sync(0xffffffffu, s1, 1);
        s1 += __shfl_xor_sync(0xffffffffu, s1, 2);
        if ((lane & 3) == 0) {
            atomicAdd(&g_sumexp[(size_t)b * Tn + row0], s0);
            atomicAdd(&g_sumexp[(size_t)b * Tn + row1], s1);
        }
    }
}

// ---------------- CE reduce + final; resets all flags for next replay ----------------
__global__ void ce_final_kernel(float* __restrict__ out)
{
    const int b = blockIdx.x;
    const int tid = threadIdx.x;
    float s = 0.0f;
    for (int t = tid; t < Tn; t += NTHREADS) {
        const int idx = b * Tn + t;
        s += logf(g_sumexp[idx]) - g_tgt[idx] * LN2;
    }
    __shared__ float red[NTHREADS];
    red[tid] = s;
    __syncthreads();
    for (int off = NTHREADS / 2; off > 0; off >>= 1) {
        if (tid < off) red[tid] += red[tid + off];
        __syncthreads();
    }
    __shared__ int last;
    if (tid == 0) {
        g_ce[b] = red[0] / (float)Tn;
        __threadfence();
        last = (atomicAdd(&g_cnt, 1) == Bn - 1);
    }
    __syncthreads();
    if (last && tid == 0) {
        float sums[En], cnt[En];
        #pragma unroll
        for (int e = 0; e < En; e++) { sums[e] = 0.0f; cnt[e] = 0.0f; }
        for (int bb = 0; bb < Bn; bb++) {
            sums[g_assign[bb]] += g_ce[bb];
            cnt[g_assign[bb]]  += 1.0f;
        }
        float tot = 0.0f;
        #pragma unroll
        for (int e = 0; e < En; e++)
            if (cnt[e] > 0.0f) tot += sums[e] / cnt[e];
        out[0] = tot;
        // reset all counters for the next graph replay
        g_cnt = 0;
        g_rdone = 0;
        g_zcnt = 0;
        #pragma unroll
        for (int bb = 0; bb < Bn; bb++) g_xcnt[bb] = 0;
        #pragma unroll
        for (int e = 0; e < En; e++) g_wcnt[e] = 0;
    }
}

// ---------------- launcher ----------------
extern "C" void kernel_launch(void* const* d_in, const int* in_sizes, int n_in,
                              void* d_out, int out_size)
{
    const float* gate = (const float*)d_in[0];
    const float* X    = (const float*)d_in[1];
    const float* Wg   = (const float*)d_in[2];
    const float* bg   = (const float*)d_in[3];
    const float* We   = (const float*)d_in[4];
    const float* be   = (const float*)d_in[5];
    const int*   tgt  = (const int*)d_in[6];
    float* out = (float*)d_out;

    cudaFuncSetAttribute(fused_kernel, cudaFuncAttributeMaxDynamicSharedMemorySize, SMEM_BYTES);

    fused_kernel<<<NB_TOTAL, FTHREADS, SMEM_BYTES>>>(
        (const float4*)X, (const float4*)We, gate, Wg, bg, be, tgt, out, out_size);

    ce_final_kernel<<<Bn, NTHREADS>>>(out);
}

// round 17
// speedup vs baseline: 1.0798x; 1.0798x over previous
#include <cuda_runtime.h>
#include <cuda_fp16.h>
#include <math.h>
#include <stdint.h>

#define Bn 32
#define Tn 1024
#define Dn 512
#define Gn 256
#define En 8
#define Vn 8192

#define BM 128
#define BN 128
#define BK 32
#define GTHREADS 128
#define NTHREADS 256

#define L2E 1.4426950408889634f
#define LN2 0.6931471805599453f

// smem strides (bytes), padded for conflict-free ldmatrix
#define A_STRIDE 80
#define B_STRIDE 272
#define A_BYTES (BM * A_STRIDE)          // 10240
#define B_BYTES (BK * B_STRIDE)          // 8704
#define STAGE_BYTES (A_BYTES + B_BYTES)  // 18944
#define NSTAGES 3
#define SM_MBAR (NSTAGES * STAGE_BYTES)  // 56832
#define SMEM_BYTES (SM_MBAR + 64)        // 56896 per CTA, 4 CTAs/SM

// prep block ranges (256 threads): 4 iters x (read 32B fp32, write 16B f16)
#define NB_Z 8
#define NB_X 2048
#define NB_W 4096
#define NB_TOTAL (NB_Z + NB_X + NB_W + 1)

// ---------------- scratch (no cudaMalloc allowed) ----------------
__device__ __half g_Xh[(size_t)Bn * Tn * Dn];
__device__ __half g_Wh[(size_t)En * Dn * Vn];
__device__ float g_sumexp[Bn * Tn];
__device__ float g_tgt[Bn * Tn];                // stores logit * log2(e)
__device__ int   g_assign[Bn];
__device__ float g_ce[Bn];
__device__ int   g_bcnt[Bn];
__device__ int   g_fcnt;

// ---------------- helpers ----------------
__device__ __forceinline__ uint32_t s2u(const void* p) {
    uint32_t a;
    asm("{ .reg .u64 t; cvta.to.shared.u64 t, %1; cvt.u32.u64 %0, t; }" : "=r"(a) : "l"(p));
    return a;
}
__device__ __forceinline__ void cp16(uint32_t dst, const void* src) {
    asm volatile("cp.async.cg.shared.global [%0], [%1], 16;" :: "r"(dst), "l"(src) : "memory");
}
__device__ __forceinline__ void mwait(uint32_t addr, uint32_t phase) {
    asm volatile(
        "{\n\t.reg .pred P;\n\t"
        "WL_%=:\n\t"
        "mbarrier.try_wait.parity.acquire.cta.shared::cta.b64 P, [%0], %1, 0x989680;\n\t"
        "@P bra WD_%=;\n\t"
        "bra WL_%=;\n\t"
        "WD_%=:\n\t}"
        :: "r"(addr), "r"(phase) : "memory");
}
__device__ __forceinline__ void mbar_init(uint32_t a, uint32_t cnt) {
    asm volatile("mbarrier.init.shared::cta.b64 [%0], %1;" :: "r"(a), "r"(cnt) : "memory");
}
__device__ __forceinline__ void mbar_arrive(uint32_t a) {
    asm volatile("mbarrier.arrive.shared::cta.b64 _, [%0];" :: "r"(a) : "memory");
}
__device__ __forceinline__ void cpasync_arrive(uint32_t a) {
    asm volatile("cp.async.mbarrier.arrive.noinc.shared::cta.b64 [%0];" :: "r"(a) : "memory");
}
__device__ __forceinline__ void ldsm_x4(uint32_t& r0, uint32_t& r1, uint32_t& r2, uint32_t& r3, uint32_t a) {
    asm volatile("ldmatrix.sync.aligned.m8n8.x4.shared.b16 {%0,%1,%2,%3}, [%4];"
                 : "=r"(r0), "=r"(r1), "=r"(r2), "=r"(r3) : "r"(a));
}
__device__ __forceinline__ void ldsm_x4t(uint32_t& r0, uint32_t& r1, uint32_t& r2, uint32_t& r3, uint32_t a) {
    asm volatile("ldmatrix.sync.aligned.m8n8.x4.trans.shared.b16 {%0,%1,%2,%3}, [%4];"
                 : "=r"(r0), "=r"(r1), "=r"(r2), "=r"(r3) : "r"(a));
}
__device__ __forceinline__ void mma_f16(uint32_t* d, const uint32_t* a, const uint32_t* b) {
    asm volatile("mma.sync.aligned.m16n8k16.row.col.f16.f16.f16.f16 "
                 "{%0,%1}, {%2,%3,%4,%5}, {%6,%7}, {%0,%1};"
                 : "+r"(d[0]), "+r"(d[1])
                 : "r"(a[0]), "r"(a[1]), "r"(a[2]), "r"(a[3]), "r"(b[0]), "r"(b[1]));
}
__device__ __forceinline__ __half2 h2ex2(__half2 x) {
    __half2 r;
    asm("ex2.approx.f16x2 %0, %1;" : "=r"(*(uint32_t*)&r) : "r"(*(uint32_t*)&x));
    return r;
}
__device__ __forceinline__ uint32_t h2u(__half2 h) { return *(uint32_t*)&h; }

// ---------------- prep: converts + zeroing + router (streaming reads) ----------------
__global__ void prep_kernel(const float4* __restrict__ X,
                            const float4* __restrict__ W,
                            const float* __restrict__ gate,
                            const float* __restrict__ Wg,
                            const float* __restrict__ bg,
                            float* __restrict__ out, int out_size)
{
    const int bid = blockIdx.x;
    const int tid = threadIdx.x;

    if (bid < NB_Z) {
        size_t base = (size_t)bid * 256 + tid;
        const size_t stride = (size_t)NB_Z * 256;
        float4 z = make_float4(0.f, 0.f, 0.f, 0.f);
        #pragma unroll
        for (int k = 0; k < 4; k++)
            ((float4*)g_sumexp)[base + k * stride] = z;
        return;
    }
    if (bid < NB_Z + NB_X) {
        size_t base = (size_t)(bid - NB_Z) * 256 + tid;
        const size_t stride = (size_t)NB_X * 256;
        float4 a[4], b[4];
        #pragma unroll
        for (int k = 0; k < 4; k++) {
            size_t j = base + k * stride;
            a[k] = __ldcs(&X[2 * j]);        // streaming: read-once fp32
            b[k] = __ldcs(&X[2 * j + 1]);
        }
        uint4* o = (uint4*)g_Xh;
        #pragma unroll
        for (int k = 0; k < 4; k++) {
            uint4 u;
            u.x = h2u(__floats2half2_rn(a[k].x, a[k].y));
            u.y = h2u(__floats2half2_rn(a[k].z, a[k].w));
            u.z = h2u(__floats2half2_rn(b[k].x, b[k].y));
            u.w = h2u(__floats2half2_rn(b[k].z, b[k].w));
            o[base + k * stride] = u;
        }
        return;
    }
    if (bid < NB_Z + NB_X + NB_W) {
        size_t base = (size_t)(bid - NB_Z - NB_X) * 256 + tid;
        const size_t stride = (size_t)NB_W * 256;
        float4 a[4], b[4];
        #pragma unroll
        for (int k = 0; k < 4; k++) {
            size_t j = base + k * stride;
            a[k] = __ldcs(&W[2 * j]);
            b[k] = __ldcs(&W[2 * j + 1]);
        }
        uint4* o = (uint4*)g_Wh;
        #pragma unroll
        for (int k = 0; k < 4; k++) {
            uint4 u;
            u.x = h2u(__floats2half2_rn(a[k].x, a[k].y));
            u.y = h2u(__floats2half2_rn(a[k].z, a[k].w));
            u.z = h2u(__floats2half2_rn(b[k].x, b[k].y));
            u.w = h2u(__floats2half2_rn(b[k].z, b[k].w));
            o[base + k * stride] = u;
        }
        return;
    }

    // ---- router block; also resets completion counters for this replay ----
    for (int i = tid; i < out_size; i += NTHREADS) out[i] = 0.0f;
    if (tid < Bn) g_bcnt[tid] = 0;
    if (tid == 0) g_fcnt = 0;

    __shared__ float logits[Bn][En];
    int i = tid / En, j = tid % En;
    float acc = bg[j];
    const float* grow = gate + i * Gn;
    #pragma unroll 4
    for (int g = 0; g < Gn; g++) acc += grow[g] * Wg[g * En + j];
    logits[i][j] = acc;
    __syncthreads();

    if (tid < Bn) {
        float mx = logits[tid][0];
        int am = 0;
        #pragma unroll
        for (int e = 1; e < En; e++) {
            float v = logits[tid][e];
            if (v > mx) { mx = v; am = e; }
        }
        float ex[En], s = 0.0f;
        #pragma unroll
        for (int e = 0; e < En; e++) { ex[e] = expf(logits[tid][e] - mx); s += ex[e]; }
        float inv = 1.0f / s;
        #pragma unroll
        for (int e = 0; e < En; e++) out[1 + Bn + tid * En + e] = ex[e] * inv;
        out[1 + tid] = (float)am;
        g_assign[tid] = am;
    }
}

// ---------------- fused HMMA GEMM + CE epilogue + per-sample CE + final ----------------
__device__ __forceinline__ void load_stage(uint32_t sA, uint32_t sB,
                                           const __half* Ag,
                                           const __half* Bg,
                                           int k0, int tid)
{
    #pragma unroll
    for (int i = 0; i < 4; i++) {
        int s = tid + i * GTHREADS;
        int row = s >> 2, j = s & 3;
        cp16(sA + (uint32_t)(row * A_STRIDE + j * 16),
             Ag + (size_t)row * Dn + k0 + j * 8);
    }
    #pragma unroll
    for (int i = 0; i < 4; i++) {
        int s = tid + i * GTHREADS;
        int kr = s >> 4, j = s & 15;
        cp16(sB + (uint32_t)(kr * B_STRIDE + j * 16),
             Bg + (size_t)(k0 + kr) * Vn + j * 8);
    }
}

__global__ void __launch_bounds__(GTHREADS, 4)
gemm_ce_kernel(const float* __restrict__ be, const int* __restrict__ tgt32,
               float* __restrict__ out)
{
    extern __shared__ char smem[];
    const uint32_t sbase = s2u(smem);
    const uint32_t mbase = sbase + SM_MBAR;
    const int tid  = threadIdx.x;
    const int wid  = tid >> 5;
    const int lane = tid & 31;
    const int wm   = wid >> 1;
    const int wn   = wid & 1;

    const int vt = blockIdx.x, tt = blockIdx.y, b = blockIdx.z;
    const int e  = g_assign[b];
    const int v0 = vt * BN;
    const int t0 = tt * BM;

    const __half* Ag = g_Xh + ((size_t)b * Tn + t0) * Dn;
    const __half* Bg = g_Wh + (size_t)e * Dn * Vn + v0;

    if (tid == 0) {
        #pragma unroll
        for (int s = 0; s < NSTAGES; s++) {
            mbar_init(mbase + s * 16,     128);
            mbar_init(mbase + s * 16 + 8, 4);
        }
    }
    __syncthreads();

    uint32_t acc[4][8][2];
    #pragma unroll
    for (int mt = 0; mt < 4; mt++)
        #pragma unroll
        for (int nt = 0; nt < 8; nt++) { acc[mt][nt][0] = 0u; acc[mt][nt][1] = 0u; }

    const uint32_t a_lane_off = (uint32_t)((lane & 15) * A_STRIDE + (lane >> 4) * 16)
                              + (uint32_t)(wm * 64 * A_STRIDE);
    const uint32_t b_lane_off = (uint32_t)((lane & 15) * B_STRIDE
                              + (wn * 64 + (lane >> 4) * 8) * 2);

    uint32_t prod_ph = 7u;
    uint32_t cons_ph = 0u;

    #pragma unroll
    for (int k = 0; k < 2; k++) {
        mwait(mbase + k * 16 + 8, (prod_ph >> k) & 1u);
        prod_ph ^= (1u << k);
        load_stage(sbase + k * STAGE_BYTES, sbase + k * STAGE_BYTES + A_BYTES,
                   Ag, Bg, k * BK, tid);
        cpasync_arrive(mbase + k * 16);
    }

    const int NCHUNK = Dn / BK;   // 16
    int ps = 2, cs = 0;
    #pragma unroll 1
    for (int c = 0; c < NCHUNK; c++) {
        if (c + 2 < NCHUNK) {
            mwait(mbase + ps * 16 + 8, (prod_ph >> ps) & 1u);
            prod_ph ^= (1u << ps);
            load_stage(sbase + ps * STAGE_BYTES, sbase + ps * STAGE_BYTES + A_BYTES,
                       Ag, Bg, (c + 2) * BK, tid);
            cpasync_arrive(mbase + ps * 16);
            if (++ps == NSTAGES) ps = 0;
        }

        mwait(mbase + cs * 16, (cons_ph >> cs) & 1u);
        cons_ph ^= (1u << cs);

        const uint32_t aBase = sbase + cs * STAGE_BYTES + a_lane_off;
        const uint32_t bBase = sbase + cs * STAGE_BYTES + A_BYTES + b_lane_off;

        #pragma unroll
        for (int kt = 0; kt < 2; kt++) {
            uint32_t af[4][4], bf[16];
            #pragma unroll
            for (int mt = 0; mt < 4; mt++)
                ldsm_x4(af[mt][0], af[mt][1], af[mt][2], af[mt][3],
                        aBase + (uint32_t)(mt * 16 * A_STRIDE + kt * 32));
            #pragma unroll
            for (int g = 0; g < 4; g++)
                ldsm_x4t(bf[g * 4 + 0], bf[g * 4 + 1], bf[g * 4 + 2], bf[g * 4 + 3],
                         bBase + (uint32_t)(kt * 16 * B_STRIDE + g * 32));
            #pragma unroll
            for (int mt = 0; mt < 4; mt++)
                #pragma unroll
                for (int nt = 0; nt < 8; nt++)
                    mma_f16(acc[mt][nt], af[mt], &bf[nt * 2]);
        }

        __syncwarp();
        if (lane == 0) mbar_arrive(mbase + cs * 16 + 8);
        if (++cs == NSTAGES) cs = 0;
    }

    // ---- epilogue ----
    const int c0 = (lane & 3) * 2;
    const int r0 = lane >> 2;
    const int vbase = v0 + wn * 64 + c0;
    const float* bias_base = be + (size_t)e * Vn + vbase;

    const __half2 l2e = __float2half2_rn(L2E);
    __half2 bsc[8];
    #pragma unroll
    for (int nt = 0; nt < 8; nt++)
        bsc[nt] = __floats2half2_rn(bias_base[nt * 8] * L2E, bias_base[nt * 8 + 1] * L2E);

    #pragma unroll
    for (int mt = 0; mt < 4; mt++) {
        const int row0 = t0 + wm * 64 + mt * 16 + r0;
        const int row1 = row0 + 8;
        const int d0 = tgt32[2 * (b * Tn + row0)] - vbase;
        const int d1 = tgt32[2 * (b * Tn + row1)] - vbase;
        float s0 = 0.0f, s1 = 0.0f;
        #pragma unroll
        for (int nt = 0; nt < 8; nt++) {
            __half2 a0 = *(__half2*)&acc[mt][nt][0];
            __half2 a1 = *(__half2*)&acc[mt][nt][1];
            __half2 t0h = __hfma2(a0, l2e, bsc[nt]);
            __half2 t1h = __hfma2(a1, l2e, bsc[nt]);
            float2 e0 = __half22float2(h2ex2(t0h));
            float2 e1 = __half22float2(h2ex2(t1h));
            s0 += e0.x + e0.y;
            s1 += e1.x + e1.y;
            if (d0 == nt * 8)     g_tgt[(size_t)b * Tn + row0] = __low2float(t0h);
            if (d0 == nt * 8 + 1) g_tgt[(size_t)b * Tn + row0] = __high2float(t0h);
            if (d1 == nt * 8)     g_tgt[(size_t)b * Tn + row1] = __low2float(t1h);
            if (d1 == nt * 8 + 1) g_tgt[(size_t)b * Tn + row1] = __high2float(t1h);
        }
        s0 += __shfl_xor_sync(0xffffffffu, s0, 1);
        s0 += __shfl_xor_sync(0xffffffffu, s0, 2);
        s1 += __shfl_xor_sync(0xffffffffu, s1, 1);
        s1 += __shfl_xor_sync(0xffffffffu, s1, 2);
        if ((lane & 3) == 0) {
            atomicAdd(&g_sumexp[(size_t)b * Tn + row0], s0);
            atomicAdd(&g_sumexp[(size_t)b * Tn + row1], s1);
        }
    }

    // ---- last-CTA-per-sample: compute ce[b]; last overall: total loss ----
    __threadfence();
    __syncthreads();
    __shared__ int lastb;
    if (tid == 0) lastb = (atomicAdd(&g_bcnt[b], 1) == 511);
    __syncthreads();
    if (!lastb) return;

    float s = 0.0f;
    for (int t = tid; t < Tn; t += GTHREADS) {
        const int idx = b * Tn + t;
        s += logf(g_sumexp[idx]) - g_tgt[idx] * LN2;
    }
    float* red = (float*)smem;           // mainloop done; smem reusable
    red[tid] = s;
    __syncthreads();
    for (int off = GTHREADS / 2; off > 0; off >>= 1) {
        if (tid < off) red[tid] += red[tid + off];
        __syncthreads();
    }
    __shared__ int lastf;
    if (tid == 0) {
        g_ce[b] = red[0] / (float)Tn;
        __threadfence();
        lastf = (atomicAdd(&g_fcnt, 1) == Bn - 1);
    }
    __syncthreads();
    if (lastf && tid == 0) {
        float sums[En], cnt[En];
        #pragma unroll
        for (int ee = 0; ee < En; ee++) { sums[ee] = 0.0f; cnt[ee] = 0.0f; }
        for (int bb = 0; bb < Bn; bb++) {
            sums[g_assign[bb]] += g_ce[bb];
            cnt[g_assign[bb]]  += 1.0f;
        }
        float tot = 0.0f;
        #pragma unroll
        for (int ee = 0; ee < En; ee++)
            if (cnt[ee] > 0.0f) tot += sums[ee] / cnt[ee];
        out[0] = tot;
    }
}

// ---------------- launcher ----------------
extern "C" void kernel_launch(void* const* d_in, const int* in_sizes, int n_in,
                              void* d_out, int out_size)
{
    const float* gate = (const float*)d_in[0];
    const float* X    = (const float*)d_in[1];
    const float* Wg   = (const float*)d_in[2];
    const float* bg   = (const float*)d_in[3];
    const float* We   = (const float*)d_in[4];
    const float* be   = (const float*)d_in[5];
    const int*   tgt  = (const int*)d_in[6];
    float* out = (float*)d_out;

    cudaFuncSetAttribute(gemm_ce_kernel, cudaFuncAttributeMaxDynamicSharedMemorySize, SMEM_BYTES);

    prep_kernel<<<NB_TOTAL, NTHREADS>>>((const float4*)X, (const float4*)We,
                                        gate, Wg, bg, out, out_size);

    dim3 grid(Vn / BN, Tn / BM, Bn);
    gemm_ce_kernel<<<grid, GTHREADS, SMEM_BYTES>>>(be, tgt, out);
}